// round 8
// baseline (speedup 1.0000x reference)
#include <cuda_runtime.h>
#include <cuda_bf16.h>

#define NPTS 262144
#define CDIM 64
#define GSZ 64
#define NH 4
#define NB 1024          // NPTS / 256 radix blocks
typedef unsigned long long u64;
typedef unsigned int u32;

// ---------------- scratch (no allocations allowed -> device globals) ----------------
__device__ u64 g_keys_a[NPTS];
__device__ u64 g_keys_b[NPTS];
__device__ u64 g_keys_c[NPTS];
__device__ u64 g_keys_d[NPTS];
__device__ u32 g_hist[256 * NB];
__device__ u32 g_base[256 * NB];
__device__ int g_ind1[NPTS];
__device__ int g_ind2[NPTS];
__device__ int g_inv1[NPTS];
__device__ int g_ind12[NPTS];
__device__ float g_x1[(size_t)NPTS * CDIM];
__device__ int g_flag;   // 1: bufA is vox_coors, 0: bufB is vox_coors

// ---------------- input disambiguation: int coords vs float pts ----------------
__global__ void detect_kernel(const u32* __restrict__ A, const u32* __restrict__ B) {
    // int32 coords are < 512 -> bit patterns < 4096. Normal-float bit patterns are huge.
    int ca = 0, cb = 0;
    for (int k = 0; k < 256; k++) {
        ca += (A[k] < 4096u) ? 1 : 0;
        cb += (B[k] < 4096u) ? 1 : 0;
    }
    g_flag = (ca >= cb) ? 1 : 0;
}

// ---------------- hilbert (Skilling AxesToTranspose + interleave), order=10 ----------------
__device__ __forceinline__ u32 hilbert3(u32 X0, u32 X1, u32 X2) {
    const u32 M = 1u << 9;
    u32 X[3] = {X0, X1, X2};
    for (u32 Q = M; Q > 1; Q >>= 1) {
        u32 P = Q - 1;
        if (X[0] & Q) X[0] ^= P;
#pragma unroll
        for (int i = 1; i < 3; i++) {
            u32 t = (X[0] ^ X[i]) & P;
            if (X[i] & Q) { X[0] ^= P; }
            else { X[0] ^= t; X[i] ^= t; }
        }
    }
    X[1] ^= X[0];
    X[2] ^= X[1];
    u32 t = 0;
    for (u32 Q = M; Q > 1; Q >>= 1)
        if (X[2] & Q) t ^= (Q - 1);
    X[0] ^= t; X[1] ^= t; X[2] ^= t;
    u32 code = 0;
#pragma unroll 1
    for (int b = 9; b >= 0; b--) {
        code = (code << 1) | ((X[0] >> b) & 1u);
        code = (code << 1) | ((X[1] >> b) & 1u);
        code = (code << 1) | ((X[2] >> b) & 1u);
    }
    return code;
}

__global__ void make_keys_kernel(const int* __restrict__ A, const int* __restrict__ B,
                                 u64* __restrict__ k1, u64* __restrict__ k2, int n) {
    int i = blockIdx.x * blockDim.x + threadIdx.x;
    if (i >= n) return;
    const int* vc = g_flag ? A : B;
    u32 b  = (u32)vc[4 * i + 0];
    u32 xx = (u32)vc[4 * i + 1];
    u32 yy = (u32)vc[4 * i + 2];
    u32 zz = (u32)vc[4 * i + 3];
    // JAX x64 is disabled by default -> reference's int64 cast is silently int32, so
    // (b << 30) overflows signed int32 for b>=2. Ascending signed order = unsigned order
    // of (bits ^ 0x80000000). Emulate exactly:
    u32 c1 = ((b << 30) | hilbert3(xx, yy, zz)) ^ 0x80000000u;
    u32 c2 = ((b << 30) | hilbert3(xx, yy + 1u, zz + 1u)) ^ 0x80000000u;
    // stable argsort == LSD radix sort over code bits (low 18 bits carry the index)
    k1[i] = ((u64)c1 << 18) | (u64)i;
    k2[i] = ((u64)c2 << 18) | (u64)i;
}

// ---------------- hand-rolled stable LSD radix sort (8-bit digits over bits [shift,shift+8)) ----
__global__ void radix_hist(const u64* __restrict__ keys, int shift) {
    __shared__ u32 h[256];
    int t = threadIdx.x;
    h[t] = 0;
    __syncthreads();
    u64 k = keys[blockIdx.x * 256 + t];
    int d = (int)((k >> shift) & 0xFF);
    atomicAdd(&h[d], 1u);
    __syncthreads();
    g_hist[t * NB + blockIdx.x] = h[t];   // row = digit, col = block
}

__global__ void radix_scan() {          // 1 block, 256 threads; digit-major exclusive scan
    __shared__ u32 rowsum[256];
    __shared__ u32 rowbase[256];
    int d = threadIdx.x;
    u32 s = 0;
    for (int b = 0; b < NB; b++) s += g_hist[d * NB + b];
    rowsum[d] = s;
    __syncthreads();
    if (d == 0) {
        u32 acc = 0;
        for (int i = 0; i < 256; i++) { rowbase[i] = acc; acc += rowsum[i]; }
    }
    __syncthreads();
    u32 acc = rowbase[d];
    for (int b = 0; b < NB; b++) {
        u32 c = g_hist[d * NB + b];
        g_base[d * NB + b] = acc;
        acc += c;
    }
}

__global__ void radix_scatter(const u64* __restrict__ in, u64* __restrict__ out, int shift) {
    __shared__ unsigned char dig[256];
    int t = threadIdx.x;
    u64 k = in[blockIdx.x * 256 + t];
    int d = (int)((k >> shift) & 0xFF);
    dig[t] = (unsigned char)d;
    __syncthreads();
    int rank = 0;
    for (int s = 0; s < t; s++) rank += (dig[s] == (unsigned char)d) ? 1 : 0;  // stable in-block rank
    out[g_base[d * NB + blockIdx.x] + rank] = k;
}

static void radix_pass(const u64* in, u64* out, int shift) {
    radix_hist<<<NB, 256>>>(in, shift);
    radix_scan<<<1, 256>>>();
    radix_scatter<<<NB, 256>>>(in, out, shift);
}

__global__ void extract_kernel(const u64* __restrict__ k1s, const u64* __restrict__ k2s,
                               int* __restrict__ ind1, int* __restrict__ ind2,
                               int* __restrict__ inv1, int n) {
    int i = blockIdx.x * blockDim.x + threadIdx.x;
    if (i >= n) return;
    int a = (int)(k1s[i] & 0x3FFFFULL);
    ind1[i] = a;
    inv1[a] = i;
    ind2[i] = (int)(k2s[i] & 0x3FFFFULL);
}

__global__ void ind12_kernel(const int* __restrict__ ind2, const int* __restrict__ inv1,
                             int* __restrict__ ind12, int n) {
    int i = blockIdx.x * blockDim.x + threadIdx.x;
    if (i >= n) return;
    ind12[i] = inv1[ind2[i]];
}

// ---------------- fused VoxFormer layer ----------------
__device__ __forceinline__ float gelu_t(float v) {
    // jax.nn.gelu default (approximate=True): tanh form
    float u = 0.7978845608028654f * (v + 0.044715f * v * v * v);
    return 0.5f * v * (1.0f + tanhf(u));
}

struct SmemAtt {
    float wq[64][16]; float wk[64][16]; float wv[64][16]; float wo[16][64];
    float ks[64][16]; float vs[64][16];
};
struct SmemFF { float fa[64][64]; float fb[64][64]; };
struct Smem {
    union { SmemAtt att; SmemFF ff; } u;   // att: 24KB, ff: 32KB
    float lns[64][65];                      // per-thread LN row (padded)
    float ssm[64][65];                      // per-thread score row (padded)
};

__global__ void __launch_bounds__(64)
layer_kernel(const float* __restrict__ xin, const int* __restrict__ gix,
             const float* __restrict__ bufA, const float* __restrict__ bufB,
             const int* __restrict__ gip,
             const float* __restrict__ Wpos, const float* __restrict__ Wqkv,
             const float* __restrict__ Wo, const float* __restrict__ Wffa,
             const float* __restrict__ Wffb, float* __restrict__ xout) {
    extern __shared__ char smem_raw[];
    Smem& S = *reinterpret_cast<Smem*>(smem_raw);
    const int i = threadIdx.x;
    const long r = (long)blockIdx.x * GSZ + i;
    const int sx = gix[r];
    const int sp = gip[r];
    const float* pts = g_flag ? bufB : bufA;   // the non-coords buffer is pts

    float x[64];
    {
        const float4* xr = (const float4*)(xin + (long)sx * 64);
#pragma unroll
        for (int c4 = 0; c4 < 16; c4++) {
            float4 t = __ldg(xr + c4);
            x[4 * c4 + 0] = t.x; x[4 * c4 + 1] = t.y; x[4 * c4 + 2] = t.z; x[4 * c4 + 3] = t.w;
        }
    }
    {   // x += p @ Wpos
        float4 pv = __ldg((const float4*)(pts + (long)sp * 4));
        float pj[4] = {pv.x, pv.y, pv.z, pv.w};
#pragma unroll
        for (int j = 0; j < 4; j++) {
            const float4* wr = (const float4*)(Wpos + j * 64);
#pragma unroll
            for (int c4 = 0; c4 < 16; c4++) {
                float4 w = __ldg(wr + c4);
                x[4 * c4 + 0] += pj[j] * w.x; x[4 * c4 + 1] += pj[j] * w.y;
                x[4 * c4 + 2] += pj[j] * w.z; x[4 * c4 + 3] += pj[j] * w.w;
            }
        }
    }
    {   // layernorm 1 -> per-thread smem row
        float s0 = 0, s1 = 0, s2 = 0, s3 = 0;
#pragma unroll
        for (int c = 0; c < 64; c += 4) { s0 += x[c]; s1 += x[c + 1]; s2 += x[c + 2]; s3 += x[c + 3]; }
        float mu = (s0 + s1 + s2 + s3) * (1.0f / 64.0f);
        float v0 = 0, v1 = 0, v2 = 0, v3 = 0;
#pragma unroll
        for (int c = 0; c < 64; c += 4) {
            float d0 = x[c] - mu, d1 = x[c + 1] - mu, d2 = x[c + 2] - mu, d3 = x[c + 3] - mu;
            v0 += d0 * d0; v1 += d1 * d1; v2 += d2 * d2; v3 += d3 * d3;
        }
        float inv = rsqrtf((v0 + v1 + v2 + v3) * (1.0f / 64.0f) + 1e-5f);
#pragma unroll
        for (int c = 0; c < 64; c++) S.lns[i][c] = (x[c] - mu) * inv;
    }

    // ---- attention, head by head; o-projection folded in per head ----
#pragma unroll 1
    for (int h = 0; h < NH; h++) {
        __syncthreads();
        {   // stage Wq/Wk/Wv slices (thread i loads row c=i) and Wo rows for this head
            const float4* qr = (const float4*)(Wqkv + i * 192 + h * 16);
            const float4* kr = (const float4*)(Wqkv + i * 192 + 64 + h * 16);
            const float4* vr = (const float4*)(Wqkv + i * 192 + 128 + h * 16);
#pragma unroll
            for (int d4 = 0; d4 < 4; d4++) {
                ((float4*)S.u.att.wq[i])[d4] = __ldg(qr + d4);
                ((float4*)S.u.att.wk[i])[d4] = __ldg(kr + d4);
                ((float4*)S.u.att.wv[i])[d4] = __ldg(vr + d4);
            }
#pragma unroll
            for (int u2 = 0; u2 < 4; u2++) {
                int l = i * 4 + u2;
                int row = l >> 4, c4 = l & 15;
                ((float4*)S.u.att.wo[row])[c4] = __ldg((const float4*)(Wo + (h * 16 + row) * 64) + c4);
            }
        }
        __syncthreads();
        float q[16] = {0}, kk[16] = {0}, vv[16] = {0};
#pragma unroll 4
        for (int c = 0; c < 64; c++) {
            float l = S.lns[i][c];
#pragma unroll
            for (int d4 = 0; d4 < 4; d4++) {
                float4 a = ((const float4*)S.u.att.wq[c])[d4];
                q[4 * d4 + 0] += l * a.x; q[4 * d4 + 1] += l * a.y; q[4 * d4 + 2] += l * a.z; q[4 * d4 + 3] += l * a.w;
                float4 b = ((const float4*)S.u.att.wk[c])[d4];
                kk[4 * d4 + 0] += l * b.x; kk[4 * d4 + 1] += l * b.y; kk[4 * d4 + 2] += l * b.z; kk[4 * d4 + 3] += l * b.w;
                float4 e = ((const float4*)S.u.att.wv[c])[d4];
                vv[4 * d4 + 0] += l * e.x; vv[4 * d4 + 1] += l * e.y; vv[4 * d4 + 2] += l * e.z; vv[4 * d4 + 3] += l * e.w;
            }
        }
#pragma unroll
        for (int d4 = 0; d4 < 4; d4++) {
            ((float4*)S.u.att.ks[i])[d4] = make_float4(kk[4 * d4], kk[4 * d4 + 1], kk[4 * d4 + 2], kk[4 * d4 + 3]);
            ((float4*)S.u.att.vs[i])[d4] = make_float4(vv[4 * d4], vv[4 * d4 + 1], vv[4 * d4 + 2], vv[4 * d4 + 3]);
        }
        __syncthreads();
        float smax = -1e30f;
#pragma unroll 4
        for (int j = 0; j < 64; j++) {
            float s = 0;
#pragma unroll
            for (int d4 = 0; d4 < 4; d4++) {
                float4 kv = ((const float4*)S.u.att.ks[j])[d4];
                s += q[4 * d4] * kv.x + q[4 * d4 + 1] * kv.y + q[4 * d4 + 2] * kv.z + q[4 * d4 + 3] * kv.w;
            }
            s *= 0.25f;  // 1/sqrt(16)
            S.ssm[i][j] = s;
            smax = fmaxf(smax, s);
        }
        float ssum = 0;
#pragma unroll 4
        for (int j = 0; j < 64; j++) {
            float e = __expf(S.ssm[i][j] - smax);
            S.ssm[i][j] = e;
            ssum += e;
        }
        float rs = 1.0f / ssum;
        float oh[16] = {0};
#pragma unroll 4
        for (int j = 0; j < 64; j++) {
            float w = S.ssm[i][j];
#pragma unroll
            for (int d4 = 0; d4 < 4; d4++) {
                float4 vj = ((const float4*)S.u.att.vs[j])[d4];
                oh[4 * d4 + 0] += w * vj.x; oh[4 * d4 + 1] += w * vj.y;
                oh[4 * d4 + 2] += w * vj.z; oh[4 * d4 + 3] += w * vj.w;
            }
        }
#pragma unroll 4
        for (int d = 0; d < 16; d++) {
            float od = oh[d] * rs;
#pragma unroll
            for (int c4 = 0; c4 < 16; c4++) {
                float4 w = ((const float4*)S.u.att.wo[d])[c4];
                x[4 * c4 + 0] += od * w.x; x[4 * c4 + 1] += od * w.y;
                x[4 * c4 + 2] += od * w.z; x[4 * c4 + 3] += od * w.w;
            }
        }
    }

    {   // layernorm 2 -> lns (reuse)
        float s0 = 0, s1 = 0, s2 = 0, s3 = 0;
#pragma unroll
        for (int c = 0; c < 64; c += 4) { s0 += x[c]; s1 += x[c + 1]; s2 += x[c + 2]; s3 += x[c + 3]; }
        float mu = (s0 + s1 + s2 + s3) * (1.0f / 64.0f);
        float v0 = 0, v1 = 0, v2 = 0, v3 = 0;
#pragma unroll
        for (int c = 0; c < 64; c += 4) {
            float d0 = x[c] - mu, d1 = x[c + 1] - mu, d2 = x[c + 2] - mu, d3 = x[c + 3] - mu;
            v0 += d0 * d0; v1 += d1 * d1; v2 += d2 * d2; v3 += d3 * d3;
        }
        float inv = rsqrtf((v0 + v1 + v2 + v3) * (1.0f / 64.0f) + 1e-5f);
#pragma unroll
        for (int c = 0; c < 64; c++) S.lns[i][c] = (x[c] - mu) * inv;
    }

    // ---- FFN in 4 chunks of 64 hidden units ----
#pragma unroll 1
    for (int t = 0; t < 4; t++) {
        __syncthreads();
        {
            const float4* far = (const float4*)(Wffa + i * 256 + t * 64);
#pragma unroll
            for (int k4 = 0; k4 < 16; k4++) ((float4*)S.u.ff.fa[i])[k4] = __ldg(far + k4);
            const float4* fbr = (const float4*)(Wffb + (t * 64 + i) * 64);
#pragma unroll
            for (int c4 = 0; c4 < 16; c4++) ((float4*)S.u.ff.fb[i])[c4] = __ldg(fbr + c4);
        }
        __syncthreads();
#pragma unroll 1
        for (int kq = 0; kq < 16; kq++) {
            float h0 = 0, h1 = 0, h2 = 0, h3 = 0;
#pragma unroll 8
            for (int c = 0; c < 64; c++) {
                float l = S.lns[i][c];
                float4 w = ((const float4*)S.u.ff.fa[c])[kq];
                h0 += l * w.x; h1 += l * w.y; h2 += l * w.z; h3 += l * w.w;
            }
            float g0 = gelu_t(h0), g1 = gelu_t(h1), g2 = gelu_t(h2), g3 = gelu_t(h3);
#pragma unroll
            for (int c4 = 0; c4 < 16; c4++) {
                float4 w0 = ((const float4*)S.u.ff.fb[4 * kq + 0])[c4];
                float4 w1 = ((const float4*)S.u.ff.fb[4 * kq + 1])[c4];
                float4 w2 = ((const float4*)S.u.ff.fb[4 * kq + 2])[c4];
                float4 w3 = ((const float4*)S.u.ff.fb[4 * kq + 3])[c4];
                x[4 * c4 + 0] += g0 * w0.x + g1 * w1.x + g2 * w2.x + g3 * w3.x;
                x[4 * c4 + 1] += g0 * w0.y + g1 * w1.y + g2 * w2.y + g3 * w3.y;
                x[4 * c4 + 2] += g0 * w0.z + g1 * w1.z + g2 * w2.z + g3 * w3.z;
                x[4 * c4 + 3] += g0 * w0.w + g1 * w1.w + g2 * w2.w + g3 * w3.w;
            }
        }
    }

    float4* orow = (float4*)(xout + r * 64);
#pragma unroll
    for (int c4 = 0; c4 < 16; c4++)
        orow[c4] = make_float4(x[4 * c4], x[4 * c4 + 1], x[4 * c4 + 2], x[4 * c4 + 3]);
}

// ---------------- launcher ----------------
extern "C" void kernel_launch(void* const* d_in, const int* in_sizes, int n_in,
                              void* d_out, int out_size) {
    // ---- classify inputs by element count (robust to slot shifts / scalar handling) ----
    const float* vox_feats = nullptr;
    const void* bufA = nullptr;  // first  [N,4]-sized buffer (pts or coors)
    const void* bufB = nullptr;  // second [N,4]-sized buffer
    const float* pos[2] = {nullptr, nullptr};
    const float* qkv[2] = {nullptr, nullptr};
    const float* wom[2] = {nullptr, nullptr};
    const float* ffm[4] = {nullptr, nullptr, nullptr, nullptr};
    int n1m = 0, npos = 0, nqkv = 0, nwo = 0, nff = 0;
    for (int idx = 0; idx < n_in; idx++) {
        int sz = in_sizes[idx];
        const void* p = d_in[idx];
        if (sz == NPTS * CDIM) vox_feats = (const float*)p;
        else if (sz == NPTS * 4) { if (n1m == 0) bufA = p; else if (n1m == 1) bufB = p; n1m++; }
        else if (sz == 4 * CDIM) { if (npos < 2) pos[npos++] = (const float*)p; }
        else if (sz == CDIM * 3 * CDIM) { if (nqkv < 2) qkv[nqkv++] = (const float*)p; }
        else if (sz == CDIM * CDIM) { if (nwo < 2) wom[nwo++] = (const float*)p; }
        else if (sz == 4 * CDIM * CDIM) { if (nff < 4) ffm[nff++] = (const float*)p; }
    }
    // appearance order within params dict: w_pos1,w_qkv1,w_o1,w_ffa1,w_ffb1,w_pos2,...
    const float* wpos1 = pos[0]; const float* wpos2 = pos[1];
    const float* wqkv1 = qkv[0]; const float* wqkv2 = qkv[1];
    const float* wo1 = wom[0];   const float* wo2 = wom[1];
    const float* wffa1 = ffm[0]; const float* wffb1 = ffm[1];
    const float* wffa2 = ffm[2]; const float* wffb2 = ffm[3];
    const int N = NPTS;

    void *pka, *pkb, *pkc, *pkd, *pi1, *pi2, *pinv, *pi12, *px1;
    cudaGetSymbolAddress(&pka, g_keys_a);
    cudaGetSymbolAddress(&pkb, g_keys_b);
    cudaGetSymbolAddress(&pkc, g_keys_c);
    cudaGetSymbolAddress(&pkd, g_keys_d);
    cudaGetSymbolAddress(&pi1, g_ind1);
    cudaGetSymbolAddress(&pi2, g_ind2);
    cudaGetSymbolAddress(&pinv, g_inv1);
    cudaGetSymbolAddress(&pi12, g_ind12);
    cudaGetSymbolAddress(&px1, g_x1);
    u64* ka = (u64*)pka; u64* kb = (u64*)pkb; u64* kc = (u64*)pkc; u64* kd = (u64*)pkd;
    int* ind1 = (int*)pi1; int* ind2 = (int*)pi2; int* inv1 = (int*)pinv; int* ind12 = (int*)pi12;
    float* x1 = (float*)px1;

    // decide on-device which of bufA/bufB holds the int coords
    detect_kernel<<<1, 1>>>((const u32*)bufA, (const u32*)bufB);

    int nb = (N + 255) / 256;
    make_keys_kernel<<<nb, 256>>>((const int*)bufA, (const int*)bufB, ka, kc, N);

    // stable argsort #1: 4 LSD passes over the 32-bit code (bits 18..49); result back in ka
    radix_pass(ka, kb, 18); radix_pass(kb, ka, 26);
    radix_pass(ka, kb, 34); radix_pass(kb, ka, 42);
    // stable argsort #2: result back in kc
    radix_pass(kc, kd, 18); radix_pass(kd, kc, 26);
    radix_pass(kc, kd, 34); radix_pass(kd, kc, 42);

    extract_kernel<<<nb, 256>>>(ka, kc, ind1, ind2, inv1, N);
    ind12_kernel<<<nb, 256>>>(ind2, inv1, ind12, N);

    cudaFuncSetAttribute(layer_kernel, cudaFuncAttributeMaxDynamicSharedMemorySize, (int)sizeof(Smem));
    int ngrp = N / GSZ;
    // layer 1: gather x and p with ind1, write x1 (order-1 sorted)
    layer_kernel<<<ngrp, 64, sizeof(Smem)>>>(vox_feats, ind1, (const float*)bufA, (const float*)bufB,
                                             ind1, wpos1, wqkv1, wo1, wffa1, wffb1, x1);
    // layer 2: gather x with ind12 (order1->order2), p with ind2; write output (order-2 sorted)
    layer_kernel<<<ngrp, 64, sizeof(Smem)>>>(x1, ind12, (const float*)bufA, (const float*)bufB,
                                             ind2, wpos2, wqkv2, wo2, wffa2, wffb2, (float*)d_out);
}

// round 9
// speedup vs baseline: 2.1274x; 2.1274x over previous
#include <cuda_runtime.h>
#include <cuda_bf16.h>

#define NPTS 262144
#define CDIM 64
#define GSZ 64
#define NH 4
#define NB 1024          // NPTS / 256 radix blocks
typedef unsigned long long u64;
typedef unsigned int u32;

// ---------------- scratch (no allocations allowed -> device globals) ----------------
__device__ u64 g_keys_a[NPTS];
__device__ u64 g_keys_b[NPTS];
__device__ u64 g_keys_c[NPTS];
__device__ u64 g_keys_d[NPTS];
__device__ u32 g_hist[256 * NB];
__device__ u32 g_base[256 * NB];
__device__ u32 g_digit_tot[256];
__device__ u32 g_digit_base[256];
__device__ int g_ind1[NPTS];
__device__ int g_ind2[NPTS];
__device__ int g_inv1[NPTS];
__device__ int g_ind12[NPTS];
__device__ float g_x1[(size_t)NPTS * CDIM];
__device__ int g_flag;   // 1: bufA is vox_coors, 0: bufB is vox_coors

// ---------------- input disambiguation: int coords vs float pts ----------------
__global__ void detect_kernel(const u32* __restrict__ A, const u32* __restrict__ B) {
    int ca = 0, cb = 0;
    for (int k = 0; k < 256; k++) {
        ca += (A[k] < 4096u) ? 1 : 0;
        cb += (B[k] < 4096u) ? 1 : 0;
    }
    g_flag = (ca >= cb) ? 1 : 0;
}

// ---------------- hilbert (Skilling AxesToTranspose + interleave), order=10 ----------------
__device__ __forceinline__ u32 hilbert3(u32 X0, u32 X1, u32 X2) {
    const u32 M = 1u << 9;
    u32 X[3] = {X0, X1, X2};
    for (u32 Q = M; Q > 1; Q >>= 1) {
        u32 P = Q - 1;
        if (X[0] & Q) X[0] ^= P;
#pragma unroll
        for (int i = 1; i < 3; i++) {
            u32 t = (X[0] ^ X[i]) & P;
            if (X[i] & Q) { X[0] ^= P; }
            else { X[0] ^= t; X[i] ^= t; }
        }
    }
    X[1] ^= X[0];
    X[2] ^= X[1];
    u32 t = 0;
    for (u32 Q = M; Q > 1; Q >>= 1)
        if (X[2] & Q) t ^= (Q - 1);
    X[0] ^= t; X[1] ^= t; X[2] ^= t;
    u32 code = 0;
#pragma unroll 1
    for (int b = 9; b >= 0; b--) {
        code = (code << 1) | ((X[0] >> b) & 1u);
        code = (code << 1) | ((X[1] >> b) & 1u);
        code = (code << 1) | ((X[2] >> b) & 1u);
    }
    return code;
}

__global__ void make_keys_kernel(const int* __restrict__ A, const int* __restrict__ B,
                                 u64* __restrict__ k1, u64* __restrict__ k2, int n) {
    int i = blockIdx.x * blockDim.x + threadIdx.x;
    if (i >= n) return;
    const int* vc = g_flag ? A : B;
    u32 b  = (u32)vc[4 * i + 0];
    u32 xx = (u32)vc[4 * i + 1];
    u32 yy = (u32)vc[4 * i + 2];
    u32 zz = (u32)vc[4 * i + 3];
    // JAX x64 disabled -> reference's int64 cast is int32; (b<<30) overflows signed for b>=2.
    // signed ascending == unsigned ascending of (bits ^ 0x80000000)
    u32 c1 = ((b << 30) | hilbert3(xx, yy, zz)) ^ 0x80000000u;
    u32 c2 = ((b << 30) | hilbert3(xx, yy + 1u, zz + 1u)) ^ 0x80000000u;
    k1[i] = ((u64)c1 << 18) | (u64)i;
    k2[i] = ((u64)c2 << 18) | (u64)i;
}

// ---------------- stable LSD radix sort, parallel scan version ----------------
__global__ void radix_hist(const u64* __restrict__ keys, int shift) {
    __shared__ u32 h[256];
    int t = threadIdx.x;
    h[t] = 0;
    __syncthreads();
    u64 k = keys[blockIdx.x * 256 + t];
    int d = (int)((k >> shift) & 0xFF);
    atomicAdd(&h[d], 1u);
    __syncthreads();
    g_hist[t * NB + blockIdx.x] = h[t];   // row = digit, col = block
}

// block d: exclusive prefix over the 1024 per-block counts of digit d (Hillis-Steele)
__global__ void radix_blockscan() {
    __shared__ u32 s[NB];
    int d = blockIdx.x, t = threadIdx.x;
    u32 v = g_hist[d * NB + t];
    s[t] = v;
    __syncthreads();
#pragma unroll
    for (int off = 1; off < NB; off <<= 1) {
        u32 add = (t >= off) ? s[t - off] : 0u;
        __syncthreads();
        s[t] += add;
        __syncthreads();
    }
    g_base[d * NB + t] = s[t] - v;        // exclusive within digit
    if (t == NB - 1) g_digit_tot[d] = s[t];
}

__global__ void radix_digitscan() {       // tiny: exclusive scan of 256 digit totals
    if (threadIdx.x == 0) {
        u32 acc = 0;
        for (int i = 0; i < 256; i++) { u32 c = g_digit_tot[i]; g_digit_base[i] = acc; acc += c; }
    }
}

__global__ void radix_scatter(const u64* __restrict__ in, u64* __restrict__ out, int shift) {
    __shared__ unsigned char dig[256];
    int t = threadIdx.x;
    u64 k = in[blockIdx.x * 256 + t];
    int d = (int)((k >> shift) & 0xFF);
    dig[t] = (unsigned char)d;
    __syncthreads();
    int rank = 0;
    for (int s = 0; s < t; s++) rank += (dig[s] == (unsigned char)d) ? 1 : 0;  // stable in-block rank
    out[g_digit_base[d] + g_base[d * NB + blockIdx.x] + rank] = k;
}

static void radix_pass(const u64* in, u64* out, int shift) {
    radix_hist<<<NB, 256>>>(in, shift);
    radix_blockscan<<<256, NB>>>();
    radix_digitscan<<<1, 32>>>();
    radix_scatter<<<NB, 256>>>(in, out, shift);
}

__global__ void extract_kernel(const u64* __restrict__ k1s, const u64* __restrict__ k2s,
                               int* __restrict__ ind1, int* __restrict__ ind2,
                               int* __restrict__ inv1, int n) {
    int i = blockIdx.x * blockDim.x + threadIdx.x;
    if (i >= n) return;
    int a = (int)(k1s[i] & 0x3FFFFULL);
    ind1[i] = a;
    inv1[a] = i;
    ind2[i] = (int)(k2s[i] & 0x3FFFFULL);
}

__global__ void ind12_kernel(const int* __restrict__ ind2, const int* __restrict__ inv1,
                             int* __restrict__ ind12, int n) {
    int i = blockIdx.x * blockDim.x + threadIdx.x;
    if (i >= n) return;
    ind12[i] = inv1[ind2[i]];
}

// ---------------- fused VoxFormer layer ----------------
__device__ __forceinline__ float gelu_t(float v) {
    float u = 0.7978845608028654f * (v + 0.044715f * v * v * v);
    return 0.5f * v * (1.0f + tanhf(u));
}

struct SmemAtt {
    float wq[64][16]; float wk[64][16]; float wv[64][16]; float wo[16][64];
    float ks[64][16]; float vs[64][16];
};
struct SmemFF { float fa[64][64]; float fb[64][64]; };
struct Smem {
    union { SmemAtt att; SmemFF ff; } u;   // att: 24KB, ff: 32KB
    float lns[64][65];                      // per-thread LN row (padded)
};                                          // total ~48.9KB -> 4 CTAs/SM

__global__ void __launch_bounds__(64, 4)
layer_kernel(const float* __restrict__ xin, const int* __restrict__ gix,
             const float* __restrict__ bufA, const float* __restrict__ bufB,
             const int* __restrict__ gip,
             const float* __restrict__ Wpos, const float* __restrict__ Wqkv,
             const float* __restrict__ Wo, const float* __restrict__ Wffa,
             const float* __restrict__ Wffb, float* __restrict__ xout) {
    extern __shared__ char smem_raw[];
    Smem& S = *reinterpret_cast<Smem*>(smem_raw);
    const int i = threadIdx.x;
    const long r = (long)blockIdx.x * GSZ + i;
    const int sx = gix[r];
    const int sp = gip[r];
    const float* pts = g_flag ? bufB : bufA;   // the non-coords buffer is pts

    float x[64];
    {
        const float4* xr = (const float4*)(xin + (long)sx * 64);
#pragma unroll
        for (int c4 = 0; c4 < 16; c4++) {
            float4 t = __ldg(xr + c4);
            x[4 * c4 + 0] = t.x; x[4 * c4 + 1] = t.y; x[4 * c4 + 2] = t.z; x[4 * c4 + 3] = t.w;
        }
    }
    {   // x += p @ Wpos
        float4 pv = __ldg((const float4*)(pts + (long)sp * 4));
        float pj[4] = {pv.x, pv.y, pv.z, pv.w};
#pragma unroll
        for (int j = 0; j < 4; j++) {
            const float4* wr = (const float4*)(Wpos + j * 64);
#pragma unroll
            for (int c4 = 0; c4 < 16; c4++) {
                float4 w = __ldg(wr + c4);
                x[4 * c4 + 0] += pj[j] * w.x; x[4 * c4 + 1] += pj[j] * w.y;
                x[4 * c4 + 2] += pj[j] * w.z; x[4 * c4 + 3] += pj[j] * w.w;
            }
        }
    }
    {   // layernorm 1 -> per-thread smem row
        float s0 = 0, s1 = 0, s2 = 0, s3 = 0;
#pragma unroll
        for (int c = 0; c < 64; c += 4) { s0 += x[c]; s1 += x[c + 1]; s2 += x[c + 2]; s3 += x[c + 3]; }
        float mu = (s0 + s1 + s2 + s3) * (1.0f / 64.0f);
        float v0 = 0, v1 = 0, v2 = 0, v3 = 0;
#pragma unroll
        for (int c = 0; c < 64; c += 4) {
            float d0 = x[c] - mu, d1 = x[c + 1] - mu, d2 = x[c + 2] - mu, d3 = x[c + 3] - mu;
            v0 += d0 * d0; v1 += d1 * d1; v2 += d2 * d2; v3 += d3 * d3;
        }
        float inv = rsqrtf((v0 + v1 + v2 + v3) * (1.0f / 64.0f) + 1e-5f);
#pragma unroll
        for (int c = 0; c < 64; c++) S.lns[i][c] = (x[c] - mu) * inv;
    }

    // ---- attention, head by head; online softmax; o-projection folded in per head ----
#pragma unroll 1
    for (int h = 0; h < NH; h++) {
        __syncthreads();
        {   // stage Wq/Wk/Wv slices (thread i loads row c=i) and Wo rows for this head
            const float4* qr = (const float4*)(Wqkv + i * 192 + h * 16);
            const float4* kr = (const float4*)(Wqkv + i * 192 + 64 + h * 16);
            const float4* vr = (const float4*)(Wqkv + i * 192 + 128 + h * 16);
#pragma unroll
            for (int d4 = 0; d4 < 4; d4++) {
                ((float4*)S.u.att.wq[i])[d4] = __ldg(qr + d4);
                ((float4*)S.u.att.wk[i])[d4] = __ldg(kr + d4);
                ((float4*)S.u.att.wv[i])[d4] = __ldg(vr + d4);
            }
#pragma unroll
            for (int u2 = 0; u2 < 4; u2++) {
                int l = i * 4 + u2;
                int row = l >> 4, c4 = l & 15;
                ((float4*)S.u.att.wo[row])[c4] = __ldg((const float4*)(Wo + (h * 16 + row) * 64) + c4);
            }
        }
        __syncthreads();
        float q[16] = {0}, kk[16] = {0}, vv[16] = {0};
#pragma unroll 4
        for (int c = 0; c < 64; c++) {
            float l = S.lns[i][c];
#pragma unroll
            for (int d4 = 0; d4 < 4; d4++) {
                float4 a = ((const float4*)S.u.att.wq[c])[d4];
                q[4 * d4 + 0] += l * a.x; q[4 * d4 + 1] += l * a.y; q[4 * d4 + 2] += l * a.z; q[4 * d4 + 3] += l * a.w;
                float4 b = ((const float4*)S.u.att.wk[c])[d4];
                kk[4 * d4 + 0] += l * b.x; kk[4 * d4 + 1] += l * b.y; kk[4 * d4 + 2] += l * b.z; kk[4 * d4 + 3] += l * b.w;
                float4 e = ((const float4*)S.u.att.wv[c])[d4];
                vv[4 * d4 + 0] += l * e.x; vv[4 * d4 + 1] += l * e.y; vv[4 * d4 + 2] += l * e.z; vv[4 * d4 + 3] += l * e.w;
            }
        }
#pragma unroll
        for (int d4 = 0; d4 < 4; d4++) {
            ((float4*)S.u.att.ks[i])[d4] = make_float4(kk[4 * d4], kk[4 * d4 + 1], kk[4 * d4 + 2], kk[4 * d4 + 3]);
            ((float4*)S.u.att.vs[i])[d4] = make_float4(vv[4 * d4], vv[4 * d4 + 1], vv[4 * d4 + 2], vv[4 * d4 + 3]);
        }
        __syncthreads();
        // online softmax-attention over j
        float m = -1e30f, l = 0.0f;
        float oh[16] = {0};
#pragma unroll 4
        for (int j = 0; j < 64; j++) {
            float s = 0;
#pragma unroll
            for (int d4 = 0; d4 < 4; d4++) {
                float4 kv = ((const float4*)S.u.att.ks[j])[d4];
                s += q[4 * d4] * kv.x + q[4 * d4 + 1] * kv.y + q[4 * d4 + 2] * kv.z + q[4 * d4 + 3] * kv.w;
            }
            s *= 0.25f;  // 1/sqrt(16)
            float nm = fmaxf(m, s);
            float corr = __expf(m - nm);
            float p = __expf(s - nm);
            l = l * corr + p;
#pragma unroll
            for (int d4 = 0; d4 < 4; d4++) {
                float4 vj = ((const float4*)S.u.att.vs[j])[d4];
                oh[4 * d4 + 0] = oh[4 * d4 + 0] * corr + p * vj.x;
                oh[4 * d4 + 1] = oh[4 * d4 + 1] * corr + p * vj.y;
                oh[4 * d4 + 2] = oh[4 * d4 + 2] * corr + p * vj.z;
                oh[4 * d4 + 3] = oh[4 * d4 + 3] * corr + p * vj.w;
            }
            m = nm;
        }
        float rs = 1.0f / l;
        // x += (oh/l) @ Wo[h*16:(h+1)*16, :]
#pragma unroll 4
        for (int d = 0; d < 16; d++) {
            float od = oh[d] * rs;
#pragma unroll
            for (int c4 = 0; c4 < 16; c4++) {
                float4 w = ((const float4*)S.u.att.wo[d])[c4];
                x[4 * c4 + 0] += od * w.x; x[4 * c4 + 1] += od * w.y;
                x[4 * c4 + 2] += od * w.z; x[4 * c4 + 3] += od * w.w;
            }
        }
    }

    {   // layernorm 2 -> lns (reuse)
        float s0 = 0, s1 = 0, s2 = 0, s3 = 0;
#pragma unroll
        for (int c = 0; c < 64; c += 4) { s0 += x[c]; s1 += x[c + 1]; s2 += x[c + 2]; s3 += x[c + 3]; }
        float mu = (s0 + s1 + s2 + s3) * (1.0f / 64.0f);
        float v0 = 0, v1 = 0, v2 = 0, v3 = 0;
#pragma unroll
        for (int c = 0; c < 64; c += 4) {
            float d0 = x[c] - mu, d1 = x[c + 1] - mu, d2 = x[c + 2] - mu, d3 = x[c + 3] - mu;
            v0 += d0 * d0; v1 += d1 * d1; v2 += d2 * d2; v3 += d3 * d3;
        }
        float inv = rsqrtf((v0 + v1 + v2 + v3) * (1.0f / 64.0f) + 1e-5f);
#pragma unroll
        for (int c = 0; c < 64; c++) S.lns[i][c] = (x[c] - mu) * inv;
    }

    // ---- FFN in 4 chunks of 64 hidden units ----
#pragma unroll 1
    for (int t = 0; t < 4; t++) {
        __syncthreads();
        {
            const float4* far = (const float4*)(Wffa + i * 256 + t * 64);
#pragma unroll
            for (int k4 = 0; k4 < 16; k4++) ((float4*)S.u.ff.fa[i])[k4] = __ldg(far + k4);
            const float4* fbr = (const float4*)(Wffb + (t * 64 + i) * 64);
#pragma unroll
            for (int c4 = 0; c4 < 16; c4++) ((float4*)S.u.ff.fb[i])[c4] = __ldg(fbr + c4);
        }
        __syncthreads();
#pragma unroll 1
        for (int kq = 0; kq < 16; kq++) {
            float h0 = 0, h1 = 0, h2 = 0, h3 = 0;
#pragma unroll 8
            for (int c = 0; c < 64; c++) {
                float l = S.lns[i][c];
                float4 w = ((const float4*)S.u.ff.fa[c])[kq];
                h0 += l * w.x; h1 += l * w.y; h2 += l * w.z; h3 += l * w.w;
            }
            float g0 = gelu_t(h0), g1 = gelu_t(h1), g2 = gelu_t(h2), g3 = gelu_t(h3);
#pragma unroll
            for (int c4 = 0; c4 < 16; c4++) {
                float4 w0 = ((const float4*)S.u.ff.fb[4 * kq + 0])[c4];
                float4 w1 = ((const float4*)S.u.ff.fb[4 * kq + 1])[c4];
                float4 w2 = ((const float4*)S.u.ff.fb[4 * kq + 2])[c4];
                float4 w3 = ((const float4*)S.u.ff.fb[4 * kq + 3])[c4];
                x[4 * c4 + 0] += g0 * w0.x + g1 * w1.x + g2 * w2.x + g3 * w3.x;
                x[4 * c4 + 1] += g0 * w0.y + g1 * w1.y + g2 * w2.y + g3 * w3.y;
                x[4 * c4 + 2] += g0 * w0.z + g1 * w1.z + g2 * w2.z + g3 * w3.z;
                x[4 * c4 + 3] += g0 * w0.w + g1 * w1.w + g2 * w2.w + g3 * w3.w;
            }
        }
    }

    float4* orow = (float4*)(xout + r * 64);
#pragma unroll
    for (int c4 = 0; c4 < 16; c4++)
        orow[c4] = make_float4(x[4 * c4], x[4 * c4 + 1], x[4 * c4 + 2], x[4 * c4 + 3]);
}

// ---------------- launcher ----------------
extern "C" void kernel_launch(void* const* d_in, const int* in_sizes, int n_in,
                              void* d_out, int out_size) {
    const float* vox_feats = nullptr;
    const void* bufA = nullptr;
    const void* bufB = nullptr;
    const float* pos[2] = {nullptr, nullptr};
    const float* qkv[2] = {nullptr, nullptr};
    const float* wom[2] = {nullptr, nullptr};
    const float* ffm[4] = {nullptr, nullptr, nullptr, nullptr};
    int n1m = 0, npos = 0, nqkv = 0, nwo = 0, nff = 0;
    for (int idx = 0; idx < n_in; idx++) {
        int sz = in_sizes[idx];
        const void* p = d_in[idx];
        if (sz == NPTS * CDIM) vox_feats = (const float*)p;
        else if (sz == NPTS * 4) { if (n1m == 0) bufA = p; else if (n1m == 1) bufB = p; n1m++; }
        else if (sz == 4 * CDIM) { if (npos < 2) pos[npos++] = (const float*)p; }
        else if (sz == CDIM * 3 * CDIM) { if (nqkv < 2) qkv[nqkv++] = (const float*)p; }
        else if (sz == CDIM * CDIM) { if (nwo < 2) wom[nwo++] = (const float*)p; }
        else if (sz == 4 * CDIM * CDIM) { if (nff < 4) ffm[nff++] = (const float*)p; }
    }
    const float* wpos1 = pos[0]; const float* wpos2 = pos[1];
    const float* wqkv1 = qkv[0]; const float* wqkv2 = qkv[1];
    const float* wo1 = wom[0];   const float* wo2 = wom[1];
    const float* wffa1 = ffm[0]; const float* wffb1 = ffm[1];
    const float* wffa2 = ffm[2]; const float* wffb2 = ffm[3];
    const int N = NPTS;

    void *pka, *pkb, *pkc, *pkd, *pi1, *pi2, *pinv, *pi12, *px1;
    cudaGetSymbolAddress(&pka, g_keys_a);
    cudaGetSymbolAddress(&pkb, g_keys_b);
    cudaGetSymbolAddress(&pkc, g_keys_c);
    cudaGetSymbolAddress(&pkd, g_keys_d);
    cudaGetSymbolAddress(&pi1, g_ind1);
    cudaGetSymbolAddress(&pi2, g_ind2);
    cudaGetSymbolAddress(&pinv, g_inv1);
    cudaGetSymbolAddress(&pi12, g_ind12);
    cudaGetSymbolAddress(&px1, g_x1);
    u64* ka = (u64*)pka; u64* kb = (u64*)pkb; u64* kc = (u64*)pkc; u64* kd = (u64*)pkd;
    int* ind1 = (int*)pi1; int* ind2 = (int*)pi2; int* inv1 = (int*)pinv; int* ind12 = (int*)pi12;
    float* x1 = (float*)px1;

    detect_kernel<<<1, 1>>>((const u32*)bufA, (const u32*)bufB);

    int nb = (N + 255) / 256;
    make_keys_kernel<<<nb, 256>>>((const int*)bufA, (const int*)bufB, ka, kc, N);

    radix_pass(ka, kb, 18); radix_pass(kb, ka, 26);
    radix_pass(ka, kb, 34); radix_pass(kb, ka, 42);
    radix_pass(kc, kd, 18); radix_pass(kd, kc, 26);
    radix_pass(kc, kd, 34); radix_pass(kd, kc, 42);

    extract_kernel<<<nb, 256>>>(ka, kc, ind1, ind2, inv1, N);
    ind12_kernel<<<nb, 256>>>(ind2, inv1, ind12, N);

    cudaFuncSetAttribute(layer_kernel, cudaFuncAttributeMaxDynamicSharedMemorySize, (int)sizeof(Smem));
    int ngrp = N / GSZ;
    layer_kernel<<<ngrp, 64, sizeof(Smem)>>>(vox_feats, ind1, (const float*)bufA, (const float*)bufB,
                                             ind1, wpos1, wqkv1, wo1, wffa1, wffb1, x1);
    layer_kernel<<<ngrp, 64, sizeof(Smem)>>>(x1, ind12, (const float*)bufA, (const float*)bufB,
                                             ind2, wpos2, wqkv2, wo2, wffa2, wffb2, (float*)d_out);
}

// round 11
// speedup vs baseline: 2.2790x; 1.0713x over previous
#include <cuda_runtime.h>
#include <cuda_bf16.h>

#define NPTS 262144
#define CDIM 64
#define GSZ 64
#define NH 4
#define NB 1024          // NPTS / 256 radix blocks
typedef unsigned long long u64;
typedef unsigned int u32;

// ---------------- scratch (no allocations allowed -> device globals) ----------------
__device__ u64 g_keys_a[NPTS];
__device__ u64 g_keys_b[NPTS];
__device__ u64 g_keys_c[NPTS];
__device__ u64 g_keys_d[NPTS];
__device__ u32 g_hist[256 * NB];
__device__ u32 g_base[256 * NB];
__device__ u32 g_digit_tot[256];
__device__ u32 g_digit_base[256];
__device__ int g_ind1[NPTS];
__device__ int g_ind2[NPTS];
__device__ int g_inv1[NPTS];
__device__ int g_ind12[NPTS];
__device__ float g_x1[(size_t)NPTS * CDIM];
__device__ int g_flag;   // 1: bufA is vox_coors, 0: bufB is vox_coors

// ---------------- packed f32x2 helpers (sm_103a; ptxas will NOT auto-fuse) ----------------
__device__ __forceinline__ u64 fma2(u64 a, u64 b, u64 c) {
    u64 d; asm("fma.rn.f32x2 %0, %1, %2, %3;" : "=l"(d) : "l"(a), "l"(b), "l"(c)); return d;
}
__device__ __forceinline__ u64 mul2(u64 a, u64 b) {
    u64 d; asm("mul.rn.f32x2 %0, %1, %2;" : "=l"(d) : "l"(a), "l"(b)); return d;
}
__device__ __forceinline__ u64 add2(u64 a, u64 b) {
    u64 d; asm("add.rn.f32x2 %0, %1, %2;" : "=l"(d) : "l"(a), "l"(b)); return d;
}
__device__ __forceinline__ u64 pack2(float lo, float hi) {
    u64 d; asm("mov.b64 %0, {%1, %2};" : "=l"(d) : "f"(lo), "f"(hi)); return d;
}
__device__ __forceinline__ void unpack2(u64 v, float& lo, float& hi) {
    asm("mov.b64 {%0, %1}, %2;" : "=f"(lo), "=f"(hi) : "l"(v));
}

// ---------------- input disambiguation: int coords vs float pts ----------------
__global__ void detect_kernel(const u32* __restrict__ A, const u32* __restrict__ B) {
    int ca = 0, cb = 0;
    for (int k = 0; k < 256; k++) {
        ca += (A[k] < 4096u) ? 1 : 0;
        cb += (B[k] < 4096u) ? 1 : 0;
    }
    g_flag = (ca >= cb) ? 1 : 0;
}

// ---------------- hilbert (Skilling AxesToTranspose + interleave), order=10 ----------------
__device__ __forceinline__ u32 hilbert3(u32 X0, u32 X1, u32 X2) {
    const u32 M = 1u << 9;
    u32 X[3] = {X0, X1, X2};
    for (u32 Q = M; Q > 1; Q >>= 1) {
        u32 P = Q - 1;
        if (X[0] & Q) X[0] ^= P;
#pragma unroll
        for (int i = 1; i < 3; i++) {
            u32 t = (X[0] ^ X[i]) & P;
            if (X[i] & Q) { X[0] ^= P; }
            else { X[0] ^= t; X[i] ^= t; }
        }
    }
    X[1] ^= X[0];
    X[2] ^= X[1];
    u32 t = 0;
    for (u32 Q = M; Q > 1; Q >>= 1)
        if (X[2] & Q) t ^= (Q - 1);
    X[0] ^= t; X[1] ^= t; X[2] ^= t;
    u32 code = 0;
#pragma unroll 1
    for (int b = 9; b >= 0; b--) {
        code = (code << 1) | ((X[0] >> b) & 1u);
        code = (code << 1) | ((X[1] >> b) & 1u);
        code = (code << 1) | ((X[2] >> b) & 1u);
    }
    return code;
}

__global__ void make_keys_kernel(const int* __restrict__ A, const int* __restrict__ B,
                                 u64* __restrict__ k1, u64* __restrict__ k2, int n) {
    int i = blockIdx.x * blockDim.x + threadIdx.x;
    if (i >= n) return;
    const int* vc = g_flag ? A : B;
    u32 b  = (u32)vc[4 * i + 0];
    u32 xx = (u32)vc[4 * i + 1];
    u32 yy = (u32)vc[4 * i + 2];
    u32 zz = (u32)vc[4 * i + 3];
    // JAX x64 disabled -> int64 cast is int32; (b<<30) overflows signed for b>=2.
    // signed ascending == unsigned ascending of (bits ^ 0x80000000)
    u32 c1 = ((b << 30) | hilbert3(xx, yy, zz)) ^ 0x80000000u;
    u32 c2 = ((b << 30) | hilbert3(xx, yy + 1u, zz + 1u)) ^ 0x80000000u;
    k1[i] = ((u64)c1 << 18) | (u64)i;
    k2[i] = ((u64)c2 << 18) | (u64)i;
}

// ---------------- stable LSD radix sort, parallel scan ----------------
__global__ void radix_hist(const u64* __restrict__ keys, int shift) {
    __shared__ u32 h[256];
    int t = threadIdx.x;
    h[t] = 0;
    __syncthreads();
    u64 k = keys[blockIdx.x * 256 + t];
    int d = (int)((k >> shift) & 0xFF);
    atomicAdd(&h[d], 1u);
    __syncthreads();
    g_hist[t * NB + blockIdx.x] = h[t];
}

__global__ void radix_blockscan() {
    __shared__ u32 s[NB];
    int d = blockIdx.x, t = threadIdx.x;
    u32 v = g_hist[d * NB + t];
    s[t] = v;
    __syncthreads();
#pragma unroll
    for (int off = 1; off < NB; off <<= 1) {
        u32 add = (t >= off) ? s[t - off] : 0u;
        __syncthreads();
        s[t] += add;
        __syncthreads();
    }
    g_base[d * NB + t] = s[t] - v;
    if (t == NB - 1) g_digit_tot[d] = s[t];
}

__global__ void radix_digitscan() {
    if (threadIdx.x == 0) {
        u32 acc = 0;
        for (int i = 0; i < 256; i++) { u32 c = g_digit_tot[i]; g_digit_base[i] = acc; acc += c; }
    }
}

__global__ void radix_scatter(const u64* __restrict__ in, u64* __restrict__ out, int shift) {
    __shared__ unsigned char dig[256];
    int t = threadIdx.x;
    u64 k = in[blockIdx.x * 256 + t];
    int d = (int)((k >> shift) & 0xFF);
    dig[t] = (unsigned char)d;
    __syncthreads();
    int rank = 0;
    for (int s = 0; s < t; s++) rank += (dig[s] == (unsigned char)d) ? 1 : 0;
    out[g_digit_base[d] + g_base[d * NB + blockIdx.x] + rank] = k;
}

static void radix_pass(const u64* in, u64* out, int shift) {
    radix_hist<<<NB, 256>>>(in, shift);
    radix_blockscan<<<256, NB>>>();
    radix_digitscan<<<1, 32>>>();
    radix_scatter<<<NB, 256>>>(in, out, shift);
}

__global__ void extract_kernel(const u64* __restrict__ k1s, const u64* __restrict__ k2s,
                               int* __restrict__ ind1, int* __restrict__ ind2,
                               int* __restrict__ inv1, int n) {
    int i = blockIdx.x * blockDim.x + threadIdx.x;
    if (i >= n) return;
    int a = (int)(k1s[i] & 0x3FFFFULL);
    ind1[i] = a;
    inv1[a] = i;
    ind2[i] = (int)(k2s[i] & 0x3FFFFULL);
}

__global__ void ind12_kernel(const int* __restrict__ ind2, const int* __restrict__ inv1,
                             int* __restrict__ ind12, int n) {
    int i = blockIdx.x * blockDim.x + threadIdx.x;
    if (i >= n) return;
    ind12[i] = inv1[ind2[i]];
}

// ---------------- fused VoxFormer layer (f32x2 packed) ----------------
__device__ __forceinline__ float gelu_t(float v) {
    float u = 0.7978845608028654f * (v + 0.044715f * v * v * v);
    float t; asm("tanh.approx.f32 %0, %1;" : "=f"(t) : "f"(u));   // MUFU.TANH
    return 0.5f * v * (1.0f + t);
}

struct SmemAtt {
    float wq[64][16]; float wk[64][16]; float wv[64][16]; float wo[16][64];
    float ks[64][16]; float vs[64][16];
};
struct SmemFF { float fa[64][64]; float fb[64][64]; };
struct Smem {
    union { SmemAtt att; SmemFF ff; } u;   // att: 24KB, ff: 32KB
    float lns[64][65];                      // per-thread LN row (padded, conflict-free)
};                                          // ~48.9KB -> 4 CTAs/SM

__global__ void __launch_bounds__(64, 4)
layer_kernel(const float* __restrict__ xin, const int* __restrict__ gix,
             const float* __restrict__ bufA, const float* __restrict__ bufB,
             const int* __restrict__ gip,
             const float* __restrict__ Wpos, const float* __restrict__ Wqkv,
             const float* __restrict__ Wo, const float* __restrict__ Wffa,
             const float* __restrict__ Wffb, float* __restrict__ xout) {
    extern __shared__ char smem_raw[];
    Smem& S = *reinterpret_cast<Smem*>(smem_raw);
    const int i = threadIdx.x;
    const long r = (long)blockIdx.x * GSZ + i;
    const int sx = gix[r];
    const int sp = gip[r];
    const float* pts = g_flag ? bufB : bufA;

    u64 X[32];   // packed x row: X[k] = (x[2k], x[2k+1])
    {
        const ulonglong2* xr = (const ulonglong2*)(xin + (long)sx * 64);
#pragma unroll
        for (int k = 0; k < 16; k++) { ulonglong2 t = xr[k]; X[2 * k] = t.x; X[2 * k + 1] = t.y; }
    }
    {   // x += p @ Wpos
        const float4 pv = *(const float4*)(pts + (long)sp * 4);
        float pj[4] = {pv.x, pv.y, pv.z, pv.w};
#pragma unroll
        for (int j = 0; j < 4; j++) {
            u64 pjp = pack2(pj[j], pj[j]);
            const ulonglong2* wr = (const ulonglong2*)(Wpos + j * 64);
#pragma unroll
            for (int k = 0; k < 16; k++) {
                ulonglong2 w = wr[k];
                X[2 * k]     = fma2(pjp, w.x, X[2 * k]);
                X[2 * k + 1] = fma2(pjp, w.y, X[2 * k + 1]);
            }
        }
    }
    {   // layernorm 1 -> scalar lns row
        u64 a0 = 0, a1 = 0, a2 = 0, a3 = 0;
#pragma unroll
        for (int k = 0; k < 8; k++) {
            a0 = add2(a0, X[4 * k]); a1 = add2(a1, X[4 * k + 1]);
            a2 = add2(a2, X[4 * k + 2]); a3 = add2(a3, X[4 * k + 3]);
        }
        float slo, shi; unpack2(add2(add2(a0, a1), add2(a2, a3)), slo, shi);
        float mu = (slo + shi) * (1.0f / 64.0f);
        u64 nmu = pack2(-mu, -mu);
        u64 v0 = 0, v1 = 0, v2 = 0, v3 = 0;
#pragma unroll
        for (int k = 0; k < 8; k++) {
            u64 d0 = add2(X[4 * k], nmu);     v0 = fma2(d0, d0, v0);
            u64 d1 = add2(X[4 * k + 1], nmu); v1 = fma2(d1, d1, v1);
            u64 d2 = add2(X[4 * k + 2], nmu); v2 = fma2(d2, d2, v2);
            u64 d3 = add2(X[4 * k + 3], nmu); v3 = fma2(d3, d3, v3);
        }
        float vlo, vhi; unpack2(add2(add2(v0, v1), add2(v2, v3)), vlo, vhi);
        float inv = rsqrtf((vlo + vhi) * (1.0f / 64.0f) + 1e-5f);
#pragma unroll
        for (int k = 0; k < 32; k++) {
            float lo, hi; unpack2(X[k], lo, hi);
            S.lns[i][2 * k] = (lo - mu) * inv;
            S.lns[i][2 * k + 1] = (hi - mu) * inv;
        }
    }

    // ---- attention, head by head; online softmax; o-projection folded in ----
#pragma unroll 1
    for (int h = 0; h < NH; h++) {
        __syncthreads();
        {   // stage Wq/Wk/Wv slices (thread i loads row c=i) and Wo rows for this head
            const float4* qr = (const float4*)(Wqkv + i * 192 + h * 16);
            const float4* kr = (const float4*)(Wqkv + i * 192 + 64 + h * 16);
            const float4* vr = (const float4*)(Wqkv + i * 192 + 128 + h * 16);
#pragma unroll
            for (int d4 = 0; d4 < 4; d4++) {
                ((float4*)S.u.att.wq[i])[d4] = __ldg(qr + d4);
                ((float4*)S.u.att.wk[i])[d4] = __ldg(kr + d4);
                ((float4*)S.u.att.wv[i])[d4] = __ldg(vr + d4);
            }
#pragma unroll
            for (int u2 = 0; u2 < 4; u2++) {
                int l = i * 4 + u2;
                int row = l >> 4, c4 = l & 15;
                ((float4*)S.u.att.wo[row])[c4] = __ldg((const float4*)(Wo + (h * 16 + row) * 64) + c4);
            }
        }
        __syncthreads();
        u64 q2[8], k2[8], v2[8];
#pragma unroll
        for (int d = 0; d < 8; d++) { q2[d] = 0; k2[d] = 0; v2[d] = 0; }
#pragma unroll 4
        for (int c = 0; c < 64; c++) {
            float l = S.lns[i][c];
            u64 lp = pack2(l, l);
            const ulonglong2* aq = (const ulonglong2*)S.u.att.wq[c];
            const ulonglong2* ak = (const ulonglong2*)S.u.att.wk[c];
            const ulonglong2* av = (const ulonglong2*)S.u.att.wv[c];
#pragma unroll
            for (int d = 0; d < 4; d++) {
                ulonglong2 wa = aq[d];
                q2[2 * d] = fma2(lp, wa.x, q2[2 * d]); q2[2 * d + 1] = fma2(lp, wa.y, q2[2 * d + 1]);
                ulonglong2 wb = ak[d];
                k2[2 * d] = fma2(lp, wb.x, k2[2 * d]); k2[2 * d + 1] = fma2(lp, wb.y, k2[2 * d + 1]);
                ulonglong2 wc = av[d];
                v2[2 * d] = fma2(lp, wc.x, v2[2 * d]); v2[2 * d + 1] = fma2(lp, wc.y, v2[2 * d + 1]);
            }
        }
#pragma unroll
        for (int d = 0; d < 4; d++) {
            ((ulonglong2*)S.u.att.ks[i])[d] = make_ulonglong2(k2[2 * d], k2[2 * d + 1]);
            ((ulonglong2*)S.u.att.vs[i])[d] = make_ulonglong2(v2[2 * d], v2[2 * d + 1]);
        }
        __syncthreads();
        // online softmax-attention
        float m = -1e30f, lsum = 0.0f;
        u64 oh2[8];
#pragma unroll
        for (int d = 0; d < 8; d++) oh2[d] = 0;
#pragma unroll 2
        for (int j = 0; j < 64; j++) {
            const ulonglong2* kr = (const ulonglong2*)S.u.att.ks[j];
            u64 sa = 0, sb = 0;
#pragma unroll
            for (int d = 0; d < 4; d++) {
                ulonglong2 kk = kr[d];
                sa = fma2(q2[2 * d], kk.x, sa);
                sb = fma2(q2[2 * d + 1], kk.y, sb);
            }
            float f0, f1; unpack2(add2(sa, sb), f0, f1);
            float s = (f0 + f1) * 0.25f;   // 1/sqrt(16)
            float nm = fmaxf(m, s);
            float corr = __expf(m - nm);
            float p = __expf(s - nm);
            lsum = lsum * corr + p;
            u64 cp = pack2(corr, corr), pp = pack2(p, p);
            const ulonglong2* vr = (const ulonglong2*)S.u.att.vs[j];
#pragma unroll
            for (int d = 0; d < 4; d++) {
                ulonglong2 vv = vr[d];
                oh2[2 * d]     = fma2(pp, vv.x, mul2(oh2[2 * d], cp));
                oh2[2 * d + 1] = fma2(pp, vv.y, mul2(oh2[2 * d + 1], cp));
            }
            m = nm;
        }
        float rs = 1.0f / lsum;
        // x += (oh/l) @ Wo  (rows 2d and 2d+1 of this head's Wo slice)
#pragma unroll
        for (int d = 0; d < 8; d++) {
            float o0, o1; unpack2(oh2[d], o0, o1);
            float s0 = o0 * rs, s1 = o1 * rs;
            u64 pA = pack2(s0, s0);
            u64 pB = pack2(s1, s1);
            const ulonglong2* w0 = (const ulonglong2*)S.u.att.wo[2 * d];
            const ulonglong2* w1 = (const ulonglong2*)S.u.att.wo[2 * d + 1];
#pragma unroll
            for (int k = 0; k < 16; k++) {
                ulonglong2 wa = w0[k], wb = w1[k];
                u64 xa = X[2 * k], xb = X[2 * k + 1];
                xa = fma2(pA, wa.x, xa); xb = fma2(pA, wa.y, xb);
                xa = fma2(pB, wb.x, xa); xb = fma2(pB, wb.y, xb);
                X[2 * k] = xa; X[2 * k + 1] = xb;
            }
        }
    }

    {   // layernorm 2 -> lns
        u64 a0 = 0, a1 = 0, a2 = 0, a3 = 0;
#pragma unroll
        for (int k = 0; k < 8; k++) {
            a0 = add2(a0, X[4 * k]); a1 = add2(a1, X[4 * k + 1]);
            a2 = add2(a2, X[4 * k + 2]); a3 = add2(a3, X[4 * k + 3]);
        }
        float slo, shi; unpack2(add2(add2(a0, a1), add2(a2, a3)), slo, shi);
        float mu = (slo + shi) * (1.0f / 64.0f);
        u64 nmu = pack2(-mu, -mu);
        u64 v0 = 0, v1 = 0, v2 = 0, v3 = 0;
#pragma unroll
        for (int k = 0; k < 8; k++) {
            u64 d0 = add2(X[4 * k], nmu);     v0 = fma2(d0, d0, v0);
            u64 d1 = add2(X[4 * k + 1], nmu); v1 = fma2(d1, d1, v1);
            u64 d2 = add2(X[4 * k + 2], nmu); v2 = fma2(d2, d2, v2);
            u64 d3 = add2(X[4 * k + 3], nmu); v3 = fma2(d3, d3, v3);
        }
        float vlo, vhi; unpack2(add2(add2(v0, v1), add2(v2, v3)), vlo, vhi);
        float inv = rsqrtf((vlo + vhi) * (1.0f / 64.0f) + 1e-5f);
#pragma unroll
        for (int k = 0; k < 32; k++) {
            float lo, hi; unpack2(X[k], lo, hi);
            S.lns[i][2 * k] = (lo - mu) * inv;
            S.lns[i][2 * k + 1] = (hi - mu) * inv;
        }
    }

    // ---- FFN in 4 chunks of 64 hidden units ----
#pragma unroll 1
    for (int t = 0; t < 4; t++) {
        __syncthreads();
        {
            const float4* far = (const float4*)(Wffa + i * 256 + t * 64);
#pragma unroll
            for (int k4 = 0; k4 < 16; k4++) ((float4*)S.u.ff.fa[i])[k4] = __ldg(far + k4);
            const float4* fbr = (const float4*)(Wffb + (t * 64 + i) * 64);
#pragma unroll
            for (int c4 = 0; c4 < 16; c4++) ((float4*)S.u.ff.fb[i])[c4] = __ldg(fbr + c4);
        }
        __syncthreads();
#pragma unroll 1
        for (int kq = 0; kq < 16; kq++) {
            u64 hA0 = 0, hB0 = 0, hA1 = 0, hB1 = 0;
#pragma unroll 4
            for (int c = 0; c < 64; c += 2) {
                float l0 = S.lns[i][c], l1 = S.lns[i][c + 1];
                u64 lp0 = pack2(l0, l0), lp1 = pack2(l1, l1);
                ulonglong2 w0 = ((const ulonglong2*)S.u.ff.fa[c])[kq];
                ulonglong2 w1 = ((const ulonglong2*)S.u.ff.fa[c + 1])[kq];
                hA0 = fma2(lp0, w0.x, hA0); hB0 = fma2(lp0, w0.y, hB0);
                hA1 = fma2(lp1, w1.x, hA1); hB1 = fma2(lp1, w1.y, hB1);
            }
            float h0, h1, h2, h3;
            unpack2(add2(hA0, hA1), h0, h1);
            unpack2(add2(hB0, hB1), h2, h3);
            float g0 = gelu_t(h0), g1 = gelu_t(h1), g2 = gelu_t(h2), g3 = gelu_t(h3);
            u64 G0 = pack2(g0, g0), G1 = pack2(g1, g1), G2 = pack2(g2, g2), G3 = pack2(g3, g3);
            const ulonglong2* f0 = (const ulonglong2*)S.u.ff.fb[4 * kq + 0];
            const ulonglong2* f1 = (const ulonglong2*)S.u.ff.fb[4 * kq + 1];
            const ulonglong2* f2 = (const ulonglong2*)S.u.ff.fb[4 * kq + 2];
            const ulonglong2* f3 = (const ulonglong2*)S.u.ff.fb[4 * kq + 3];
#pragma unroll
            for (int k = 0; k < 16; k++) {
                ulonglong2 a = f0[k], b = f1[k], c2 = f2[k], d2 = f3[k];
                u64 xa = X[2 * k], xb = X[2 * k + 1];
                xa = fma2(G0, a.x, xa);  xb = fma2(G0, a.y, xb);
                xa = fma2(G1, b.x, xa);  xb = fma2(G1, b.y, xb);
                xa = fma2(G2, c2.x, xa); xb = fma2(G2, c2.y, xb);
                xa = fma2(G3, d2.x, xa); xb = fma2(G3, d2.y, xb);
                X[2 * k] = xa; X[2 * k + 1] = xb;
            }
        }
    }

    ulonglong2* orow = (ulonglong2*)(xout + r * 64);
#pragma unroll
    for (int k = 0; k < 16; k++) orow[k] = make_ulonglong2(X[2 * k], X[2 * k + 1]);
}

// ---------------- launcher ----------------
extern "C" void kernel_launch(void* const* d_in, const int* in_sizes, int n_in,
                              void* d_out, int out_size) {
    const float* vox_feats = nullptr;
    const void* bufA = nullptr;
    const void* bufB = nullptr;
    const float* pos[2] = {nullptr, nullptr};
    const float* qkv[2] = {nullptr, nullptr};
    const float* wom[2] = {nullptr, nullptr};
    const float* ffm[4] = {nullptr, nullptr, nullptr, nullptr};
    int n1m = 0, npos = 0, nqkv = 0, nwo = 0, nff = 0;
    for (int idx = 0; idx < n_in; idx++) {
        int sz = in_sizes[idx];
        const void* p = d_in[idx];
        if (sz == NPTS * CDIM) vox_feats = (const float*)p;
        else if (sz == NPTS * 4) { if (n1m == 0) bufA = p; else if (n1m == 1) bufB = p; n1m++; }
        else if (sz == 4 * CDIM) { if (npos < 2) pos[npos++] = (const float*)p; }
        else if (sz == CDIM * 3 * CDIM) { if (nqkv < 2) qkv[nqkv++] = (const float*)p; }
        else if (sz == CDIM * CDIM) { if (nwo < 2) wom[nwo++] = (const float*)p; }
        else if (sz == 4 * CDIM * CDIM) { if (nff < 4) ffm[nff++] = (const float*)p; }
    }
    const float* wpos1 = pos[0]; const float* wpos2 = pos[1];
    const float* wqkv1 = qkv[0]; const float* wqkv2 = qkv[1];
    const float* wo1 = wom[0];   const float* wo2 = wom[1];
    const float* wffa1 = ffm[0]; const float* wffb1 = ffm[1];
    const float* wffa2 = ffm[2]; const float* wffb2 = ffm[3];
    const int N = NPTS;

    void *pka, *pkb, *pkc, *pkd, *pi1, *pi2, *pinv, *pi12, *px1;
    cudaGetSymbolAddress(&pka, g_keys_a);
    cudaGetSymbolAddress(&pkb, g_keys_b);
    cudaGetSymbolAddress(&pkc, g_keys_c);
    cudaGetSymbolAddress(&pkd, g_keys_d);
    cudaGetSymbolAddress(&pi1, g_ind1);
    cudaGetSymbolAddress(&pi2, g_ind2);
    cudaGetSymbolAddress(&pinv, g_inv1);
    cudaGetSymbolAddress(&pi12, g_ind12);
    cudaGetSymbolAddress(&px1, g_x1);
    u64* ka = (u64*)pka; u64* kb = (u64*)pkb; u64* kc = (u64*)pkc; u64* kd = (u64*)pkd;
    int* ind1 = (int*)pi1; int* ind2 = (int*)pi2; int* inv1 = (int*)pinv; int* ind12 = (int*)pi12;
    float* x1 = (float*)px1;

    detect_kernel<<<1, 1>>>((const u32*)bufA, (const u32*)bufB);

    int nb = (N + 255) / 256;
    make_keys_kernel<<<nb, 256>>>((const int*)bufA, (const int*)bufB, ka, kc, N);

    radix_pass(ka, kb, 18); radix_pass(kb, ka, 26);
    radix_pass(ka, kb, 34); radix_pass(kb, ka, 42);
    radix_pass(kc, kd, 18); radix_pass(kd, kc, 26);
    radix_pass(kc, kd, 34); radix_pass(kd, kc, 42);

    extract_kernel<<<nb, 256>>>(ka, kc, ind1, ind2, inv1, N);
    ind12_kernel<<<nb, 256>>>(ind2, inv1, ind12, N);

    cudaFuncSetAttribute(layer_kernel, cudaFuncAttributeMaxDynamicSharedMemorySize, (int)sizeof(Smem));
    int ngrp = N / GSZ;
    layer_kernel<<<ngrp, 64, sizeof(Smem)>>>(vox_feats, ind1, (const float*)bufA, (const float*)bufB,
                                             ind1, wpos1, wqkv1, wo1, wffa1, wffb1, x1);
    layer_kernel<<<ngrp, 64, sizeof(Smem)>>>(x1, ind12, (const float*)bufA, (const float*)bufB,
                                             ind2, wpos2, wqkv2, wo2, wffa2, wffb2, (float*)d_out);
}